// round 12
// baseline (speedup 1.0000x reference)
#include <cuda_runtime.h>
#include <math_constants.h>

#define N_IN   16384
#define NCONV  128
#define KMAX   11
#define TPB    256
#define CPB    16    // convs per block (processed block-cooperatively)
#define CHUNK  65    // 65 == 1 (mod 32) -> conflict-free lanes for any dilation

__device__ __forceinline__ float warpReduceMax(float v) {
#pragma unroll
    for (int o = 16; o > 0; o >>= 1)
        v = fmaxf(v, __shfl_xor_sync(0xffffffffu, v, o));
    return v;
}
__device__ __forceinline__ int warpReduceSum(int v) {
#pragma unroll
    for (int o = 16; o > 0; o >>= 1)
        v += __shfl_xor_sync(0xffffffffu, v, o);
    return v;
}

__device__ __forceinline__ int meta_at(const void* arr, int c, bool is64) {
    if (is64) return (int)((const long long*)arr)[c];
    return ((const int*)arr)[c];
}

// One K-output group: history P holds the previous K taps (P[s+1..K-1] are the
// K-1 newest), C receives K fresh taps (batched, immediate-offset LDS).
// Output s window = P[s+1..K-1] ++ C[0..s].
template <int K>
__device__ __forceinline__ void group_fast(
    const float* __restrict__ w, float bias,
    const float*& ptr, int d,
    float (&P)[K], float (&C)[K], float& mx, int& neg)
{
#pragma unroll
    for (int s = 0; s < K; s++) C[s] = ptr[s * d];
    ptr += K * d;
#pragma unroll
    for (int s = 0; s < K; s++) {
        float y = bias;
#pragma unroll
        for (int t = 0; t < K; t++) {
            float tap = (s + 1 + t < K) ? P[s + 1 + t] : C[s + 1 + t - K];
            y = fmaf(w[t], tap, y);
        }
        mx = fmaxf(mx, y);
        neg += (int)(__float_as_uint(y) >> 31);
    }
}

template <int K>
__device__ __forceinline__ void group_clamped(
    const float* __restrict__ xs,
    const float* __restrict__ w, float bias,
    int& ix, int d,
    float (&P)[K], float (&C)[K], float& mx, int& neg)
{
#pragma unroll
    for (int s = 0; s < K; s++) {
        unsigned ui = min((unsigned)(ix + s * d), (unsigned)N_IN);
        C[s] = xs[ui];
    }
    ix += K * d;
#pragma unroll
    for (int s = 0; s < K; s++) {
        float y = bias;
#pragma unroll
        for (int t = 0; t < K; t++) {
            float tap = (s + 1 + t < K) ? P[s + 1 + t] : C[s + 1 + t - K];
            y = fmaf(w[t], tap, y);
        }
        mx = fmaxf(mx, y);
        neg += (int)(__float_as_uint(y) >> 31);
    }
}

// ---- fast ring: no bounds checks; loads exactly len+K-1 taps,
// max address i0+(len+K-2)*d ----
template <int K>
__device__ __forceinline__ void ring_fast(
    const float* __restrict__ xs, const float* __restrict__ w, float bias,
    int i0, int d, int len, float& mx, int& neg)
{
    const float* ptr = xs + i0;
    float P[K], C[K];
#pragma unroll
    for (int s = 1; s < K; s++) P[s] = ptr[(s - 1) * d];
    ptr += (K - 1) * d;

    const int full = len / K;
    const int rem  = len - full * K;

    int g = full;
#pragma unroll 1
    while (g >= 2) {                       // ping-pong: no history copies
        group_fast<K>(w, bias, ptr, d, P, C, mx, neg);
        group_fast<K>(w, bias, ptr, d, C, P, mx, neg);
        g -= 2;
    }
    if (g == 1) {
        group_fast<K>(w, bias, ptr, d, P, C, mx, neg);
#pragma unroll
        for (int t = 1; t < K; t++) P[t] = C[t];
    }

    // exact-length tail (shift register over P[1..K-1])
    float z[K - 1];
#pragma unroll
    for (int t = 0; t < K - 1; t++) z[t] = P[t + 1];
#pragma unroll 1
    for (int s = 0; s < rem; s++) {
        float nw = *ptr; ptr += d;
        float y = fmaf(w[0], z[0], bias);
#pragma unroll
        for (int t = 1; t < K; t++)
            y = fmaf(w[t], (t < K - 1) ? z[t] : nw, y);
        mx = fmaxf(mx, y);
        neg += (int)(__float_as_uint(y) >> 31);
#pragma unroll
        for (int t = 0; t < K - 2; t++) z[t] = z[t + 1];
        z[K - 2] = nw;
    }
}

// ---- clamped ring: OOB taps -> zero sentinel xs[N_IN] ----
template <int K>
__device__ __forceinline__ void ring_clamped(
    const float* __restrict__ xs, const float* __restrict__ w, float bias,
    int i0, int d, int len, float& mx, int& neg)
{
    int ix = i0;
    float P[K], C[K];
#pragma unroll
    for (int s = 1; s < K; s++) {
        unsigned ui = min((unsigned)(ix + (s - 1) * d), (unsigned)N_IN);
        P[s] = xs[ui];
    }
    ix += (K - 1) * d;

    const int full = len / K;
    const int rem  = len - full * K;

    int g = full;
#pragma unroll 1
    while (g >= 2) {
        group_clamped<K>(xs, w, bias, ix, d, P, C, mx, neg);
        group_clamped<K>(xs, w, bias, ix, d, C, P, mx, neg);
        g -= 2;
    }
    if (g == 1) {
        group_clamped<K>(xs, w, bias, ix, d, P, C, mx, neg);
#pragma unroll
        for (int t = 1; t < K; t++) P[t] = C[t];
    }

    float z[K - 1];
#pragma unroll
    for (int t = 0; t < K - 1; t++) z[t] = P[t + 1];
#pragma unroll 1
    for (int s = 0; s < rem; s++) {
        unsigned ui = min((unsigned)ix, (unsigned)N_IN);
        float nw = xs[ui]; ix += d;
        float y = fmaf(w[0], z[0], bias);
#pragma unroll
        for (int t = 1; t < K; t++)
            y = fmaf(w[t], (t < K - 1) ? z[t] : nw, y);
        mx = fmaxf(mx, y);
        neg += (int)(__float_as_uint(y) >> 31);
#pragma unroll
        for (int t = 0; t < K - 2; t++) z[t] = z[t + 1];
        z[K - 2] = nw;
    }
}

// Segment [ma, mb) of phase r: clamped head | fast | clamped tail.
// If the fast portion is short, one clamped ring beats 3 preloads.
template <int K>
__device__ __forceinline__ void seg3(
    const float* __restrict__ xs, const float* __restrict__ w, float bias,
    int r, int d, int ma, int mb, int f_hi_p1, float& mx, int& neg)
{
    const int b1 = min(mb, max(ma, 0));
    const int b2 = max(b1, min(mb, f_hi_p1));
    if (b2 - b1 >= 2 * K) {
        if (ma < b1) ring_clamped<K>(xs, w, bias, r + ma * d, d, b1 - ma, mx, neg);
        ring_fast<K>(xs, w, bias, r + b1 * d, d, b2 - b1, mx, neg);
        if (b2 < mb) ring_clamped<K>(xs, w, bias, r + b2 * d, d, mb - b2, mx, neg);
    } else {
        ring_clamped<K>(xs, w, bias, r + ma * d, d, mb - ma, mx, neg);
    }
}

// Whole block cooperates on one conv. Outputs u = t - p = r + m*d.
template <int K>
__device__ __forceinline__ void conv_feat_block(
    const float* __restrict__ xs,
    const float* __restrict__ wrow, float bias,
    int d, int p, int L,
    float& mx_out, int& neg_out)
{
    float w[K];
#pragma unroll
    for (int j = 0; j < K; j++) w[j] = wrow[j];

    float mx = -CUDART_INF_F;
    int   neg = 0;
    const int tid = threadIdx.x;

    // Hoisted divides:
    //  m_lo(r) = -(pq + (prm + r >= d)); m_hi(r) = aq - (r > arm)
    //  f_hi(r) = nq - (r > nrm) - (K-1)  [last output with all taps in range]
    const int A   = L - 1 - p;
    const int pq  = p / d,          prm = p - pq * d;
    const int aq  = A / d,          arm = A - aq * d;
    const int nq  = (N_IN - 1) / d, nrm = (N_IN - 1) - nq * d;

    if (d >= TPB) {
        // phase per thread, full phase in one shot
        for (int r = tid; r < d; r += TPB) {
            const int m_lo = -(pq + ((prm + r) >= d ? 1 : 0));
            const int m_hi = aq - (r > arm ? 1 : 0);
            if (m_hi < m_lo) continue;
            const int f_hi = nq - (r > nrm ? 1 : 0) - (K - 1);
            seg3<K>(xs, w, bias, r, d, m_lo, m_hi + 1, f_hi + 1, mx, neg);
        }
    } else {
        const int maxlen = (L + d - 1) / d;
        const int nQ     = (maxlen + CHUNK - 1) / CHUNK;
        const int nItems = d * nQ;
        const float rd   = 1.0f / (float)d;

        for (int j = tid; j < nItems; j += TPB) {
            // q = j / d, r = j % d via float reciprocal (+/-1 fixup)
            int q = (int)((float)j * rd);
            int r = j - q * d;
            if (r < 0)       { r += d; q--; }
            else if (r >= d) { r -= d; q++; }

            const int m_lo = -(pq + ((prm + r) >= d ? 1 : 0));
            const int m_hi = aq - (r > arm ? 1 : 0);
            const int m0   = m_lo + q * CHUNK;
            const int m1   = min(m0 + CHUNK, m_hi + 1);
            if (m1 <= m0) continue;
            const int f_hi = nq - (r > nrm ? 1 : 0) - (K - 1);
            seg3<K>(xs, w, bias, r, d, m0, m1, f_hi + 1, mx, neg);
        }
    }

    mx_out = mx;
    neg_out = neg;
}

__global__ void __launch_bounds__(TPB, 3)
feat_kernel(const float* __restrict__ x,
            const float* __restrict__ W,
            const float* __restrict__ B,
            const void* __restrict__ KS,
            const void* __restrict__ DS,
            const void* __restrict__ PS,
            float* __restrict__ out)
{
    extern __shared__ float xs[];   // N_IN + zero sentinel
    const int b = blockIdx.y;

    {
        const float4* xr4 = (const float4*)(x + (size_t)b * N_IN);
        float4* xs4 = (float4*)xs;
        for (int i = threadIdx.x; i < N_IN / 4; i += TPB)
            xs4[i] = xr4[i];
        if (threadIdx.x == 0) xs[N_IN] = 0.0f;
    }

    __shared__ float rmax[TPB / 32];
    __shared__ int   rneg[TPB / 32];
    __syncthreads();

    // int64 vs int32 metadata: kernel_sizes[0] in {7,9,11}; for int64 the
    // second 32-bit word is 0, for int32 it's kernel_sizes[1] (>=7).
    const bool is64 = (((const int*)KS)[1] == 0);

    const int c0 = blockIdx.x * CPB;
    for (int c = c0; c < c0 + CPB; ++c) {
        const int k = meta_at(KS, c, is64);
        const int d = meta_at(DS, c, is64);
        const int p = meta_at(PS, c, is64);
        const int L = N_IN + 2 * p - d * (k - 1);

        const float* wrow = W + c * KMAX;
        const float bias  = B[c];

        float mx; int neg;
        if (k == 7)       conv_feat_block<7 >(xs, wrow, bias, d, p, L, mx, neg);
        else if (k == 9)  conv_feat_block<9 >(xs, wrow, bias, d, p, L, mx, neg);
        else              conv_feat_block<11>(xs, wrow, bias, d, p, L, mx, neg);

        mx  = warpReduceMax(mx);
        neg = warpReduceSum(neg);
        const int warp = threadIdx.x >> 5;
        const int lane = threadIdx.x & 31;
        if (lane == 0) { rmax[warp] = mx; rneg[warp] = neg; }
        __syncthreads();
        if (threadIdx.x == 0) {
            float m = rmax[0]; int n = rneg[0];
#pragma unroll
            for (int i = 1; i < TPB / 32; i++) {
                m = fmaxf(m, rmax[i]);
                n += rneg[i];
            }
            const size_t base = (size_t)b * (2 * NCONV) + 2 * c;
            out[base]     = m;
            out[base + 1] = (float)(L - n) / (float)L;
        }
        __syncthreads();
    }
}

extern "C" void kernel_launch(void* const* d_in, const int* in_sizes, int n_in,
                              void* d_out, int out_size)
{
    const float* x  = (const float*)d_in[0];
    const float* W  = (const float*)d_in[1];
    const float* B  = (const float*)d_in[2];
    const void*  KS = d_in[3];
    const void*  DS = d_in[4];
    const void*  PS = d_in[5];
    float* out = (float*)d_out;

    const int batch = in_sizes[0] / N_IN;   // 256

    const size_t smem = (N_IN + 16) * sizeof(float);
    cudaFuncSetAttribute(feat_kernel,
                         cudaFuncAttributeMaxDynamicSharedMemorySize,
                         (int)smem);

    dim3 grid(NCONV / CPB, batch);
    feat_kernel<<<grid, TPB, smem>>>(x, W, B, KS, DS, PS, out);
}